// round 10
// baseline (speedup 1.0000x reference)
#include <cuda_runtime.h>
#include <cstdint>
#include <cstddef>

#define N_NODES 10000
#define N_EDGES 160000
#define C110F 0.57735026918962576f
#define C111F 0.70710678118654752f
#define EPSF  1e-5f

// ---------------- device scratch ----------------
__device__ float    g_q[(size_t)N_NODES * 40];
__device__ float    g_attn[N_EDGES];
__device__ float    g_ex[N_EDGES];
__device__ float    g_vout[(size_t)N_EDGES * 40];
__device__ unsigned g_menc[N_NODES];
__device__ float    g_denom[N_NODES];
__device__ float    g_upd[(size_t)N_NODES * 40];
__device__ float    g_stats[40];   // [0:16) sum_s  [16:32) sumsq_s  [32:40) sum |v|^2

__device__ __forceinline__ unsigned enc_f(float f) {
    unsigned u = __float_as_uint(f);
    return (u & 0x80000000u) ? ~u : (u | 0x80000000u);
}
__device__ __forceinline__ float dec_f(unsigned u) {
    return (u & 0x80000000u) ? __uint_as_float(u ^ 0x80000000u)
                             : __uint_as_float(~u);
}

// ---------------- kernel 0: init ----------------
__global__ void init_kernel() {
    int i = blockIdx.x * 256 + threadIdx.x;
    if (i < N_NODES) { g_menc[i] = 0x007FFFFFu; g_denom[i] = 0.f; }
    if (i < 40) g_stats[i] = 0.f;
    if (i < N_NODES * 40) g_upd[i] = 0.f;
}

// ---------------- probe: keeps edge_kernel as the 4th launch (ncu lands there) ----------------
__global__ void probe_kernel() {}

// ---------------- kernel 1: q = irreps_linear ----------------
__global__ void q_kernel(const float* __restrict__ atom,
                         const float* __restrict__ Wqs,
                         const float* __restrict__ Wqv) {
    __shared__ float ws[256];
    __shared__ float wv[64];
    int t = threadIdx.x;
    ws[t] = Wqs[t];
    if (t < 64) wv[t] = Wqv[t];
    __syncthreads();
    int n = blockIdx.x * 256 + t;
    if (n >= N_NODES) return;
    float x[40];
#pragma unroll
    for (int j = 0; j < 40; j++) x[j] = atom[(size_t)n * 40 + j];
    float q[40];
#pragma unroll
    for (int o = 0; o < 16; o++) {
        float a = 0.f;
#pragma unroll
        for (int i = 0; i < 16; i++) a += x[i] * ws[i * 16 + o];
        q[o] = a;
    }
#pragma unroll
    for (int o = 0; o < 8; o++) {
#pragma unroll
        for (int d = 0; d < 3; d++) {
            float a = 0.f;
#pragma unroll
            for (int i = 0; i < 8; i++) a += x[16 + i * 3 + d] * wv[i * 8 + o];
            q[16 + o * 3 + d] = a;
        }
    }
#pragma unroll
    for (int j = 0; j < 40; j++) g_q[(size_t)n * 40 + j] = q[j];
}

// ---------------- kernel 2: fused edge kernel ----------------
struct EK_Smem {
    float HkT[32][68];    // relu(ef@kw1+kb1) transposed [c][e]
    float HvT[32][68];
    float wpk[32][68];    // k W2 panel stage; also efT before layer 1
    float wpv[32][68];    // v W2 panel stage
    float pbk[64][68];    // k panel GEMM output [e][col]
    float pbv[64][68];    // v panel GEMM output
    float pe[64][129];    // per-edge data
    float b2k[640];
    float b2v[640];
    int   dst[64];
    int   src[64];
};
// pe layout: [0:16) q_s | [16:40) q_v o*3+d | [40:56) x_s | [56:80) x_v
//            [80:84) sh | [84:92) dot | [92:116) cross | [116:124) qvs

__global__ void __launch_bounds__(256, 2)
edge_kernel(const float* __restrict__ atom, const float* __restrict__ ef,
            const float* __restrict__ sh,
            const float* __restrict__ kw1, const float* __restrict__ kb1,
            const float* __restrict__ kw2, const float* __restrict__ kb2,
            const float* __restrict__ vw1, const float* __restrict__ vb1,
            const float* __restrict__ vw2, const float* __restrict__ vb2,
            const int* __restrict__ eidx) {
    extern __shared__ char smraw[];
    EK_Smem& sm = *reinterpret_cast<EK_Smem*>(smraw);
    const int tid = threadIdx.x;
    const int e0  = blockIdx.x * 64;

    if (tid < 64)        sm.dst[tid]      = eidx[e0 + tid];
    else if (tid < 128)  sm.src[tid - 64] = eidx[N_EDGES + e0 + (tid - 64)];
    for (int i = tid; i < 640; i += 256) { sm.b2k[i] = kb2[i]; sm.b2v[i] = vb2[i]; }
    for (int idx = tid; idx < 64 * 32; idx += 256) {
        int e = idx >> 5, c = idx & 31;
        sm.wpk[c][e] = ef[(size_t)(e0 + e) * 32 + c];     // efT
    }
    __syncthreads();

    // ---- layer 1: H = relu(ef @ w1 + b1), stored transposed ----
    {
        int mat = tid >> 7;           // 0:k 1:v
        int t   = tid & 127;
        int og  = t & 7;              // 4 output cols
        int eg  = t >> 3;             // 4 edges
        const float* w1 = mat ? vw1 : kw1;
        const float* b1 = mat ? vb1 : kb1;
        float acc[4][4];
#pragma unroll
        for (int i = 0; i < 4; i++)
#pragma unroll
            for (int j = 0; j < 4; j++) acc[i][j] = 0.f;
#pragma unroll
        for (int c = 0; c < 32; c++) {
            float4 e4 = *reinterpret_cast<const float4*>(&sm.wpk[c][eg * 4]);
            float4 w4 = *reinterpret_cast<const float4*>(&w1[c * 32 + og * 4]);
            float ee[4] = {e4.x, e4.y, e4.z, e4.w};
            float ww[4] = {w4.x, w4.y, w4.z, w4.w};
#pragma unroll
            for (int i = 0; i < 4; i++)
#pragma unroll
                for (int j = 0; j < 4; j++) acc[i][j] += ee[i] * ww[j];
        }
        float (*HT)[68] = mat ? sm.HvT : sm.HkT;
#pragma unroll
        for (int j = 0; j < 4; j++) {
            float b = b1[og * 4 + j];
#pragma unroll
            for (int i = 0; i < 4; i++)
                HT[og * 4 + j][eg * 4 + i] = fmaxf(acc[i][j] + b, 0.f);
        }
    }

    // ---- gather per-edge q / x / sh ----
    for (int idx = tid; idx < 64 * 40; idx += 256) {
        int e = idx / 40, j = idx - e * 40;
        sm.pe[e][j]      = g_q[(size_t)sm.src[e] * 40 + j];
        sm.pe[e][40 + j] = atom[(size_t)sm.dst[e] * 40 + j];
    }
    if (tid < 64) {
        float4 s4 = *reinterpret_cast<const float4*>(&sh[(size_t)(e0 + tid) * 4]);
        sm.pe[tid][80] = s4.x; sm.pe[tid][81] = s4.y;
        sm.pe[tid][82] = s4.z; sm.pe[tid][83] = s4.w;
    }
    __syncthreads();

    // ---- per-edge precompute: dot, cross, qvs ----
#pragma unroll
    for (int k = 0; k < 2; k++) {
        int task = tid + k * 256;            // 512 = 64 edges * 8 i
        int e = task >> 3, i = task & 7;
        float* pe = sm.pe[e];
        float a0 = pe[56 + i * 3], a1 = pe[56 + i * 3 + 1], a2 = pe[56 + i * 3 + 2];
        float b0 = pe[81], b1 = pe[82], b2 = pe[83];
        pe[84 + i]         = a0 * b0 + a1 * b1 + a2 * b2;    // dot
        pe[92 + i * 3 + 0] = a1 * b2 - a2 * b1;              // cross
        pe[92 + i * 3 + 1] = a2 * b0 - a0 * b2;
        pe[92 + i * 3 + 2] = a0 * b1 - a1 * b0;
        float q0 = pe[16 + i * 3], q1 = pe[16 + i * 3 + 1], q2 = pe[16 + i * 3 + 2];
        pe[116 + i] = q0 * b0 + q1 * b1 + q2 * b2;           // qvs
    }

    // GEMM mapping: mats split across threads. 128 threads per mat,
    // each thread: 4 edges x 8 cols. Warp lanes span 8 col-groups ->
    // each W LDS.128 covers 8 unique 16B chunks = 1 wavefront.
    const int gmat = tid >> 7;            // 0:k 1:v
    const int gt   = tid & 127;
    const int gtx  = gt & 7;              // col group (8 cols)
    const int gey  = gt >> 3;             // edge group (4 edges)
    float (*GHT)[68] = gmat ? sm.HvT : sm.HkT;
    float (*GWP)[68] = gmat ? sm.wpv : sm.wpk;
    float (*GPB)[68] = gmat ? sm.pbv : sm.pbk;
    const float* gb2 = gmat ? sm.b2v : sm.b2k;

    const int e_c = tid >> 2, part = tid & 3; // consume coords

    float attn_part = 0.f;
    float vs_acc[4] = {0.f, 0.f, 0.f, 0.f};
    float vv_acc[6] = {0.f, 0.f, 0.f, 0.f, 0.f, 0.f};

    __syncthreads();

    for (int p = 0; p < 10; p++) {
        // stage both W2 panels (32 x 64 each). Safe without extra barrier:
        // all threads passed the post-GEMM barrier of the previous panel
        // before their consume, and stage only overwrites wpk/wpv which the
        // previous GEMM finished reading before that barrier.
#pragma unroll
        for (int k = 0; k < 2; k++) {
            int idx = tid + k * 256;      // 512 float4 slots per panel
            int c = idx >> 4, col = (idx & 15) * 4;
            float4 a = *reinterpret_cast<const float4*>(&kw2[c * 640 + p * 64 + col]);
            float4 b = *reinterpret_cast<const float4*>(&vw2[c * 640 + p * 64 + col]);
            *reinterpret_cast<float4*>(&sm.wpk[c][col]) = a;
            *reinterpret_cast<float4*>(&sm.wpv[c][col]) = b;
        }
        __syncthreads();

        // GEMM: 64x64x32 per mat, this thread's mat only. 4 edges x 8 cols.
        {
            float acc[4][8];
#pragma unroll
            for (int i = 0; i < 4; i++)
#pragma unroll
                for (int j = 0; j < 8; j++) acc[i][j] = 0.f;
#pragma unroll
            for (int c = 0; c < 32; c++) {
                float4 h4 = *reinterpret_cast<const float4*>(&GHT[c][gey * 4]);
                float4 wa = *reinterpret_cast<const float4*>(&GWP[c][gtx * 8]);
                float4 wb = *reinterpret_cast<const float4*>(&GWP[c][gtx * 8 + 4]);
                float hh[4] = {h4.x, h4.y, h4.z, h4.w};
                float wl[8] = {wa.x, wa.y, wa.z, wa.w, wb.x, wb.y, wb.z, wb.w};
#pragma unroll
                for (int i = 0; i < 4; i++)
#pragma unroll
                    for (int j = 0; j < 8; j++) acc[i][j] += hh[i] * wl[j];
            }
            float bb[8];
#pragma unroll
            for (int j = 0; j < 8; j++) bb[j] = gb2[p * 64 + gtx * 8 + j];
#pragma unroll
            for (int i = 0; i < 4; i++) {
                *reinterpret_cast<float4*>(&GPB[gey * 4 + i][gtx * 8]) =
                    make_float4(acc[i][0] + bb[0], acc[i][1] + bb[1],
                                acc[i][2] + bb[2], acc[i][3] + bb[3]);
                *reinterpret_cast<float4*>(&GPB[gey * 4 + i][gtx * 8 + 4]) =
                    make_float4(acc[i][4] + bb[4], acc[i][5] + bb[5],
                                acc[i][6] + bb[6], acc[i][7] + bb[7]);
            }
        }
        __syncthreads();

        // ---- consume both panels into tensor-product contractions ----
        {
            float* pe = sm.pe[e_c];
            float shs = pe[80];
#pragma unroll
            for (int mat = 0; mat < 2; mat++) {
                float* pb = mat ? sm.pbv[e_c] : sm.pbk[e_c];
                if (p < 6) {
                    float q0 = pe[part * 4 + 0], q1 = pe[part * 4 + 1];
                    float q2 = pe[part * 4 + 2], q3 = pe[part * 4 + 3];
#pragma unroll
                    for (int ii = 0; ii < 4; ii++) {
                        float fac = (p < 4) ? pe[40 + p * 4 + ii] * shs
                                            : C110F * pe[84 + (p - 4) * 4 + ii];
                        const float* w = &pb[ii * 16 + part * 4];
                        if (mat == 0) {
                            attn_part += fac * (w[0] * q0 + w[1] * q1 + w[2] * q2 + w[3] * q3);
                        } else {
                            vs_acc[0] += w[0] * fac; vs_acc[1] += w[1] * fac;
                            vs_acc[2] += w[2] * fac; vs_acc[3] += w[3] * fac;
                        }
                    }
                } else {
                    int oA = part * 2, oB = part * 2 + 1;
                    float qsA = pe[116 + oA], qsB = pe[116 + oB];
                    float qA0 = pe[16 + oA * 3], qA1 = pe[16 + oA * 3 + 1], qA2 = pe[16 + oA * 3 + 2];
                    float qB0 = pe[16 + oB * 3], qB1 = pe[16 + oB * 3 + 1], qB2 = pe[16 + oB * 3 + 2];
                    float sv0 = pe[81], sv1 = pe[82], sv2 = pe[83];
#pragma unroll
                    for (int ii = 0; ii < 8; ii++) {
                        float wa = pb[ii * 8 + oA], wb = pb[ii * 8 + oB];
                        if (p < 8) {
                            float xs = pe[40 + (p - 6) * 8 + ii];
                            if (mat == 0) {
                                attn_part += xs * (wa * qsA + wb * qsB);
                            } else {
                                float ta = wa * xs, tb = wb * xs;
                                vv_acc[0] += ta * sv0; vv_acc[1] += ta * sv1; vv_acc[2] += ta * sv2;
                                vv_acc[3] += tb * sv0; vv_acc[4] += tb * sv1; vv_acc[5] += tb * sv2;
                            }
                        } else {
                            float v0, v1, v2, ca, cb;
                            if (p == 8) {
                                v0 = pe[56 + ii * 3]; v1 = pe[56 + ii * 3 + 1]; v2 = pe[56 + ii * 3 + 2];
                                ca = wa * shs; cb = wb * shs;
                            } else {
                                v0 = pe[92 + ii * 3]; v1 = pe[92 + ii * 3 + 1]; v2 = pe[92 + ii * 3 + 2];
                                ca = wa * C111F; cb = wb * C111F;
                            }
                            if (mat == 0) {
                                attn_part += ca * (v0 * qA0 + v1 * qA1 + v2 * qA2)
                                           + cb * (v0 * qB0 + v1 * qB1 + v2 * qB2);
                            } else {
                                vv_acc[0] += ca * v0; vv_acc[1] += ca * v1; vv_acc[2] += ca * v2;
                                vv_acc[3] += cb * v0; vv_acc[4] += cb * v1; vv_acc[5] += cb * v2;
                            }
                        }
                    }
                }
            }
        }
    } // panels

    // finalize attn
    {
        float a = attn_part;
        a += __shfl_down_sync(0xffffffffu, a, 2, 4);
        a += __shfl_down_sync(0xffffffffu, a, 1, 4);
        if (part == 0) {
            g_attn[e0 + e_c] = a;
            atomicMax(&g_menc[sm.src[e_c]], enc_f(a));
        }
    }
    // finalize v
    {
        size_t base = (size_t)(e0 + e_c) * 40;
#pragma unroll
        for (int j = 0; j < 4; j++) g_vout[base + part * 4 + j] = vs_acc[j];
#pragma unroll
        for (int oo = 0; oo < 2; oo++)
#pragma unroll
            for (int d = 0; d < 3; d++)
                g_vout[base + 16 + (part * 2 + oo) * 3 + d] = vv_acc[oo * 3 + d];
    }
}

// ---------------- kernel 3: exp + denom ----------------
__global__ void exp_kernel(const int* __restrict__ eidx) {
    int e = blockIdx.x * 256 + threadIdx.x;
    if (e >= N_EDGES) return;
    int s = eidx[N_EDGES + e];
    float m = dec_f(g_menc[s]);
    float ex = expf(g_attn[e] - m);
    g_ex[e] = ex;
    atomicAdd(&g_denom[s], ex);
}

// ---------------- kernel 4: scatter e*v ----------------
__global__ void scatter_kernel(const int* __restrict__ eidx) {
    int t = blockIdx.x * 256 + threadIdx.x;   // e*40 + j
    if (t >= N_EDGES * 40) return;
    int e = t / 40;
    int j = t - e * 40;
    int s = eidx[N_EDGES + e];
    atomicAdd(&g_upd[(size_t)s * 40 + j], g_ex[e] * g_vout[(size_t)t]);
}

// ---------------- kernel 5: node finalize + bn stats ----------------
__global__ void node_kernel(const float* __restrict__ atom) {
    __shared__ float red[40];
    int t = threadIdx.x;
    if (t < 40) red[t] = 0.f;
    __syncthreads();
    int n = blockIdx.x * 256 + t;
    if (n < N_NODES) {
        float dnm = g_denom[n];
        float inv = dnm > 0.f ? 1.f / dnm : 0.f;
        float y[40];
#pragma unroll
        for (int j = 0; j < 40; j++) {
            y[j] = atom[(size_t)n * 40 + j] + g_upd[(size_t)n * 40 + j] * inv;
            g_upd[(size_t)n * 40 + j] = y[j];
        }
#pragma unroll
        for (int j = 0; j < 16; j++) {
            atomicAdd(&red[j], y[j]);
            atomicAdd(&red[16 + j], y[j] * y[j]);
        }
#pragma unroll
        for (int o = 0; o < 8; o++) {
            float sq = y[16 + o * 3] * y[16 + o * 3]
                     + y[16 + o * 3 + 1] * y[16 + o * 3 + 1]
                     + y[16 + o * 3 + 2] * y[16 + o * 3 + 2];
            atomicAdd(&red[32 + o], sq);
        }
    }
    __syncthreads();
    if (t < 40) atomicAdd(&g_stats[t], red[t]);
}

// ---------------- kernel 6: batchnorm apply ----------------
__global__ void final_kernel(const float* __restrict__ bnws,
                             const float* __restrict__ bnbs,
                             const float* __restrict__ bnwv,
                             float* __restrict__ out, int n_elems) {
    int i = blockIdx.x * 256 + threadIdx.x;
    if (i >= n_elems) return;
    int n = i / 40;
    int j = i - n * 40;
    float y = g_upd[(size_t)i];
    float r;
    if (j < 16) {
        float mu  = g_stats[j] * (1.f / N_NODES);
        float var = g_stats[16 + j] * (1.f / N_NODES) - mu * mu;
        r = (y - mu) * rsqrtf(var + EPSF) * bnws[j] + bnbs[j];
    } else {
        int o = (j - 16) / 3;
        float norm = g_stats[32 + o] * (1.f / (3.f * N_NODES));
        r = y * rsqrtf(norm + EPSF) * bnwv[o];
    }
    out[i] = r;
}

// ---------------- launch ----------------
extern "C" void kernel_launch(void* const* d_in, const int* in_sizes, int n_in,
                              void* d_out, int out_size) {
    const float* atom = (const float*)d_in[0];
    const float* ef   = (const float*)d_in[1];
    const float* sh   = (const float*)d_in[2];
    const float* Wqs  = (const float*)d_in[3];
    const float* Wqv  = (const float*)d_in[4];
    const float* kw1  = (const float*)d_in[5];
    const float* kb1  = (const float*)d_in[6];
    const float* kw2  = (const float*)d_in[7];
    const float* kb2  = (const float*)d_in[8];
    const float* vw1  = (const float*)d_in[9];
    const float* vb1  = (const float*)d_in[10];
    const float* vw2  = (const float*)d_in[11];
    const float* vb2  = (const float*)d_in[12];
    const float* bnws = (const float*)d_in[13];
    const float* bnbs = (const float*)d_in[14];
    const float* bnwv = (const float*)d_in[15];
    const int*   eidx = (const int*)d_in[16];
    float* out = (float*)d_out;

    cudaFuncSetAttribute(edge_kernel, cudaFuncAttributeMaxDynamicSharedMemorySize,
                         (int)sizeof(EK_Smem));

    init_kernel<<<1563, 256>>>();                              // launch 1
    q_kernel<<<(N_NODES + 255) / 256, 256>>>(atom, Wqs, Wqv);  // launch 2
    probe_kernel<<<1, 32>>>();                                 // launch 3 (ncu alignment)
    edge_kernel<<<N_EDGES / 64, 256, sizeof(EK_Smem)>>>(       // launch 4 <- profiled
        atom, ef, sh, kw1, kb1, kw2, kb2, vw1, vb1, vw2, vb2, eidx);
    exp_kernel<<<(N_EDGES + 255) / 256, 256>>>(eidx);
    scatter_kernel<<<(N_EDGES * 40 + 255) / 256, 256>>>(eidx);
    node_kernel<<<(N_NODES + 255) / 256, 256>>>(atom);

    long long ef_elems = (long long)N_EDGES * 32;
    int n_node_elems = out_size;
    bool has_ef = (out_size > ef_elems);
    if (has_ef) n_node_elems = (int)(out_size - ef_elems);

    final_kernel<<<(n_node_elems + 255) / 256, 256>>>(bnws, bnbs, bnwv, out, n_node_elems);
    if (has_ef)
        cudaMemcpyAsync(out + n_node_elems, ef, (size_t)ef_elems * sizeof(float),
                        cudaMemcpyDeviceToDevice);
}

// round 11
// speedup vs baseline: 1.2296x; 1.2296x over previous
#include <cuda_runtime.h>
#include <cstdint>
#include <cstddef>

#define N_NODES 10000
#define N_EDGES 160000
#define C110F 0.57735026918962576f
#define C111F 0.70710678118654752f
#define EPSF  1e-5f

// ---------------- device scratch ----------------
__device__ float    g_q[(size_t)N_NODES * 40];
__device__ float    g_attn[N_EDGES];
__device__ float    g_ex[N_EDGES];
__device__ float    g_vout[(size_t)N_EDGES * 40];
__device__ unsigned g_menc[N_NODES];
__device__ float    g_denom[N_NODES];
__device__ float    g_upd[(size_t)N_NODES * 40];
__device__ float    g_stats[40];   // [0:16) sum_s  [16:32) sumsq_s  [32:40) sum |v|^2

__device__ __forceinline__ unsigned enc_f(float f) {
    unsigned u = __float_as_uint(f);
    return (u & 0x80000000u) ? ~u : (u | 0x80000000u);
}
__device__ __forceinline__ float dec_f(unsigned u) {
    return (u & 0x80000000u) ? __uint_as_float(u ^ 0x80000000u)
                             : __uint_as_float(~u);
}

// ---------------- kernel 0: init ----------------
__global__ void init_kernel() {
    int i = blockIdx.x * 256 + threadIdx.x;
    if (i < N_NODES) { g_menc[i] = 0x007FFFFFu; g_denom[i] = 0.f; }
    if (i < 40) g_stats[i] = 0.f;
    if (i < N_NODES * 40) g_upd[i] = 0.f;
}

// ---------------- probe: keeps edge_kernel as the 4th launch (ncu lands there) ----------------
__global__ void probe_kernel() {}

// ---------------- kernel 1: q = irreps_linear ----------------
__global__ void q_kernel(const float* __restrict__ atom,
                         const float* __restrict__ Wqs,
                         const float* __restrict__ Wqv) {
    __shared__ float ws[256];
    __shared__ float wv[64];
    int t = threadIdx.x;
    ws[t] = Wqs[t];
    if (t < 64) wv[t] = Wqv[t];
    __syncthreads();
    int n = blockIdx.x * 256 + t;
    if (n >= N_NODES) return;
    float x[40];
#pragma unroll
    for (int j = 0; j < 40; j++) x[j] = atom[(size_t)n * 40 + j];
    float q[40];
#pragma unroll
    for (int o = 0; o < 16; o++) {
        float a = 0.f;
#pragma unroll
        for (int i = 0; i < 16; i++) a += x[i] * ws[i * 16 + o];
        q[o] = a;
    }
#pragma unroll
    for (int o = 0; o < 8; o++) {
#pragma unroll
        for (int d = 0; d < 3; d++) {
            float a = 0.f;
#pragma unroll
            for (int i = 0; i < 8; i++) a += x[16 + i * 3 + d] * wv[i * 8 + o];
            q[16 + o * 3 + d] = a;
        }
    }
#pragma unroll
    for (int j = 0; j < 40; j++) g_q[(size_t)n * 40 + j] = q[j];
}

// ---------------- kernel 2: fused edge kernel ----------------
struct EK_Smem {
    float HkT[32][68];    // relu(ef@kw1+kb1) transposed [c][e]
    float HvT[32][68];
    float wpk[32][68];    // k W2 panel stage; also efT before layer 1
    float wpv[32][68];    // v W2 panel stage
    float pbk[64][68];    // k panel GEMM output [e][col]
    float pbv[64][68];    // v panel GEMM output
    float pe[64][129];    // per-edge data
    float b2k[640];
    float b2v[640];
    int   dst[64];
    int   src[64];
};
// pe layout: [0:16) q_s | [16:40) q_v o*3+d | [40:56) x_s | [56:80) x_v
//            [80:84) sh | [84:92) dot | [92:116) cross | [116:124) qvs

__global__ void __launch_bounds__(256, 2)
edge_kernel(const float* __restrict__ atom, const float* __restrict__ ef,
            const float* __restrict__ sh,
            const float* __restrict__ kw1, const float* __restrict__ kb1,
            const float* __restrict__ kw2, const float* __restrict__ kb2,
            const float* __restrict__ vw1, const float* __restrict__ vb1,
            const float* __restrict__ vw2, const float* __restrict__ vb2,
            const int* __restrict__ eidx) {
    extern __shared__ char smraw[];
    EK_Smem& sm = *reinterpret_cast<EK_Smem*>(smraw);
    const int tid = threadIdx.x;
    const int e0  = blockIdx.x * 64;

    if (tid < 64)        sm.dst[tid]      = eidx[e0 + tid];
    else if (tid < 128)  sm.src[tid - 64] = eidx[N_EDGES + e0 + (tid - 64)];
    for (int i = tid; i < 640; i += 256) { sm.b2k[i] = kb2[i]; sm.b2v[i] = vb2[i]; }
    for (int idx = tid; idx < 64 * 32; idx += 256) {
        int e = idx >> 5, c = idx & 31;
        sm.wpk[c][e] = ef[(size_t)(e0 + e) * 32 + c];     // efT
    }
    __syncthreads();

    // ---- layer 1: H = relu(ef @ w1 + b1), stored transposed ----
    {
        int mat = tid >> 7;           // 0:k 1:v
        int t   = tid & 127;
        int og  = t & 7;              // 4 output cols
        int eg  = t >> 3;             // 4 edges
        const float* w1 = mat ? vw1 : kw1;
        const float* b1 = mat ? vb1 : kb1;
        float acc[4][4];
#pragma unroll
        for (int i = 0; i < 4; i++)
#pragma unroll
            for (int j = 0; j < 4; j++) acc[i][j] = 0.f;
#pragma unroll
        for (int c = 0; c < 32; c++) {
            float4 e4 = *reinterpret_cast<const float4*>(&sm.wpk[c][eg * 4]);
            float4 w4 = *reinterpret_cast<const float4*>(&w1[c * 32 + og * 4]);
            float ee[4] = {e4.x, e4.y, e4.z, e4.w};
            float ww[4] = {w4.x, w4.y, w4.z, w4.w};
#pragma unroll
            for (int i = 0; i < 4; i++)
#pragma unroll
                for (int j = 0; j < 4; j++) acc[i][j] += ee[i] * ww[j];
        }
        float (*HT)[68] = mat ? sm.HvT : sm.HkT;
#pragma unroll
        for (int j = 0; j < 4; j++) {
            float b = b1[og * 4 + j];
#pragma unroll
            for (int i = 0; i < 4; i++)
                HT[og * 4 + j][eg * 4 + i] = fmaxf(acc[i][j] + b, 0.f);
        }
    }

    // ---- gather per-edge q / x / sh ----
    for (int idx = tid; idx < 64 * 40; idx += 256) {
        int e = idx / 40, j = idx - e * 40;
        sm.pe[e][j]      = g_q[(size_t)sm.src[e] * 40 + j];
        sm.pe[e][40 + j] = atom[(size_t)sm.dst[e] * 40 + j];
    }
    if (tid < 64) {
        float4 s4 = *reinterpret_cast<const float4*>(&sh[(size_t)(e0 + tid) * 4]);
        sm.pe[tid][80] = s4.x; sm.pe[tid][81] = s4.y;
        sm.pe[tid][82] = s4.z; sm.pe[tid][83] = s4.w;
    }
    __syncthreads();

    // ---- per-edge precompute: dot, cross, qvs ----
#pragma unroll
    for (int k = 0; k < 2; k++) {
        int task = tid + k * 256;            // 512 = 64 edges * 8 i
        int e = task >> 3, i = task & 7;
        float* pe = sm.pe[e];
        float a0 = pe[56 + i * 3], a1 = pe[56 + i * 3 + 1], a2 = pe[56 + i * 3 + 2];
        float b0 = pe[81], b1 = pe[82], b2 = pe[83];
        pe[84 + i]         = a0 * b0 + a1 * b1 + a2 * b2;    // dot
        pe[92 + i * 3 + 0] = a1 * b2 - a2 * b1;              // cross
        pe[92 + i * 3 + 1] = a2 * b0 - a0 * b2;
        pe[92 + i * 3 + 2] = a0 * b1 - a1 * b0;
        float q0 = pe[16 + i * 3], q1 = pe[16 + i * 3 + 1], q2 = pe[16 + i * 3 + 2];
        pe[116 + i] = q0 * b0 + q1 * b1 + q2 * b2;           // qvs
    }

    // GEMM lane mapping (register-neutral 4x4 tile, wavefront-optimal):
    // warp w, lane l:  colg = ((w&3)<<2)|(l&3)   -> W LDS.128 spans 4 consecutive
    //                  eg   = ((w>>2)<<3)|(l>>2) -> h LDS.128 spans 128B contiguous
    // => 2 wavefronts per k-iter per mat (was 3).
    const int wrp = tid >> 5, lan = tid & 31;
    const int colg = ((wrp & 3) << 2) | (lan & 3);
    const int eg   = ((wrp >> 2) << 3) | (lan >> 2);

    const int e_c = tid >> 2, part = tid & 3; // consume coords

    float attn_part = 0.f;
    float vs_acc[4] = {0.f, 0.f, 0.f, 0.f};
    float vv_acc[6] = {0.f, 0.f, 0.f, 0.f, 0.f, 0.f};

    __syncthreads();

    for (int p = 0; p < 10; p++) {
        // stage both W2 panels (32 x 64 each). Safe without loop-top barrier:
        // stage follows this thread's consume of the previous panel, and all
        // threads passed the post-GEMM barrier before consuming.
#pragma unroll
        for (int k = 0; k < 2; k++) {
            int idx = tid + k * 256;      // 512 float4 slots per panel
            int c = idx >> 4, col = (idx & 15) * 4;
            float4 a = *reinterpret_cast<const float4*>(&kw2[c * 640 + p * 64 + col]);
            float4 b = *reinterpret_cast<const float4*>(&vw2[c * 640 + p * 64 + col]);
            *reinterpret_cast<float4*>(&sm.wpk[c][col]) = a;
            *reinterpret_cast<float4*>(&sm.wpv[c][col]) = b;
        }
        __syncthreads();

        // k GEMM: 64x64x32, 4x4 micro-tile
        {
            float acc[4][4];
#pragma unroll
            for (int i = 0; i < 4; i++)
#pragma unroll
                for (int j = 0; j < 4; j++) acc[i][j] = 0.f;
#pragma unroll
            for (int c = 0; c < 32; c++) {
                float4 h4 = *reinterpret_cast<const float4*>(&sm.HkT[c][eg * 4]);
                float4 w4 = *reinterpret_cast<const float4*>(&sm.wpk[c][colg * 4]);
                float hh[4] = {h4.x, h4.y, h4.z, h4.w};
                float ww[4] = {w4.x, w4.y, w4.z, w4.w};
#pragma unroll
                for (int i = 0; i < 4; i++)
#pragma unroll
                    for (int j = 0; j < 4; j++) acc[i][j] += hh[i] * ww[j];
            }
            float4 b4 = *reinterpret_cast<const float4*>(&sm.b2k[p * 64 + colg * 4]);
#pragma unroll
            for (int i = 0; i < 4; i++)
                *reinterpret_cast<float4*>(&sm.pbk[eg * 4 + i][colg * 4]) =
                    make_float4(acc[i][0] + b4.x, acc[i][1] + b4.y,
                                acc[i][2] + b4.z, acc[i][3] + b4.w);
        }
        // v GEMM
        {
            float acc[4][4];
#pragma unroll
            for (int i = 0; i < 4; i++)
#pragma unroll
                for (int j = 0; j < 4; j++) acc[i][j] = 0.f;
#pragma unroll
            for (int c = 0; c < 32; c++) {
                float4 h4 = *reinterpret_cast<const float4*>(&sm.HvT[c][eg * 4]);
                float4 w4 = *reinterpret_cast<const float4*>(&sm.wpv[c][colg * 4]);
                float hh[4] = {h4.x, h4.y, h4.z, h4.w};
                float ww[4] = {w4.x, w4.y, w4.z, w4.w};
#pragma unroll
                for (int i = 0; i < 4; i++)
#pragma unroll
                    for (int j = 0; j < 4; j++) acc[i][j] += hh[i] * ww[j];
            }
            float4 b4 = *reinterpret_cast<const float4*>(&sm.b2v[p * 64 + colg * 4]);
#pragma unroll
            for (int i = 0; i < 4; i++)
                *reinterpret_cast<float4*>(&sm.pbv[eg * 4 + i][colg * 4]) =
                    make_float4(acc[i][0] + b4.x, acc[i][1] + b4.y,
                                acc[i][2] + b4.z, acc[i][3] + b4.w);
        }
        __syncthreads();

        // ---- consume both panels (vectorized LDS) ----
        {
            float* pe = sm.pe[e_c];
            float shs = pe[80];
#pragma unroll
            for (int mat = 0; mat < 2; mat++) {
                float* pb = mat ? sm.pbv[e_c] : sm.pbk[e_c];
                if (p < 6) {
                    float q0 = pe[part * 4 + 0], q1 = pe[part * 4 + 1];
                    float q2 = pe[part * 4 + 2], q3 = pe[part * 4 + 3];
#pragma unroll
                    for (int ii = 0; ii < 4; ii++) {
                        float fac = (p < 4) ? pe[40 + p * 4 + ii] * shs
                                            : C110F * pe[84 + (p - 4) * 4 + ii];
                        float4 w4 = *reinterpret_cast<const float4*>(&pb[ii * 16 + part * 4]);
                        if (mat == 0) {
                            attn_part += fac * (w4.x * q0 + w4.y * q1 + w4.z * q2 + w4.w * q3);
                        } else {
                            vs_acc[0] += w4.x * fac; vs_acc[1] += w4.y * fac;
                            vs_acc[2] += w4.z * fac; vs_acc[3] += w4.w * fac;
                        }
                    }
                } else {
                    int oA = part * 2, oB = part * 2 + 1;
                    float qsA = pe[116 + oA], qsB = pe[116 + oB];
                    float qA0 = pe[16 + oA * 3], qA1 = pe[16 + oA * 3 + 1], qA2 = pe[16 + oA * 3 + 2];
                    float qB0 = pe[16 + oB * 3], qB1 = pe[16 + oB * 3 + 1], qB2 = pe[16 + oB * 3 + 2];
                    float sv0 = pe[81], sv1 = pe[82], sv2 = pe[83];
#pragma unroll
                    for (int ii = 0; ii < 8; ii++) {
                        float2 w2 = *reinterpret_cast<const float2*>(&pb[ii * 8 + oA]);
                        float wa = w2.x, wb = w2.y;
                        if (p < 8) {
                            float xs = pe[40 + (p - 6) * 8 + ii];
                            if (mat == 0) {
                                attn_part += xs * (wa * qsA + wb * qsB);
                            } else {
                                float ta = wa * xs, tb = wb * xs;
                                vv_acc[0] += ta * sv0; vv_acc[1] += ta * sv1; vv_acc[2] += ta * sv2;
                                vv_acc[3] += tb * sv0; vv_acc[4] += tb * sv1; vv_acc[5] += tb * sv2;
                            }
                        } else {
                            float v0, v1, v2, ca, cb;
                            if (p == 8) {
                                v0 = pe[56 + ii * 3]; v1 = pe[56 + ii * 3 + 1]; v2 = pe[56 + ii * 3 + 2];
                                ca = wa * shs; cb = wb * shs;
                            } else {
                                v0 = pe[92 + ii * 3]; v1 = pe[92 + ii * 3 + 1]; v2 = pe[92 + ii * 3 + 2];
                                ca = wa * C111F; cb = wb * C111F;
                            }
                            if (mat == 0) {
                                attn_part += ca * (v0 * qA0 + v1 * qA1 + v2 * qA2)
                                           + cb * (v0 * qB0 + v1 * qB1 + v2 * qB2);
                            } else {
                                vv_acc[0] += ca * v0; vv_acc[1] += ca * v1; vv_acc[2] += ca * v2;
                                vv_acc[3] += cb * v0; vv_acc[4] += cb * v1; vv_acc[5] += cb * v2;
                            }
                        }
                    }
                }
            }
        }
    } // panels

    // finalize attn
    {
        float a = attn_part;
        a += __shfl_down_sync(0xffffffffu, a, 2, 4);
        a += __shfl_down_sync(0xffffffffu, a, 1, 4);
        if (part == 0) {
            g_attn[e0 + e_c] = a;
            atomicMax(&g_menc[sm.src[e_c]], enc_f(a));
        }
    }
    // finalize v
    {
        size_t base = (size_t)(e0 + e_c) * 40;
#pragma unroll
        for (int j = 0; j < 4; j++) g_vout[base + part * 4 + j] = vs_acc[j];
#pragma unroll
        for (int oo = 0; oo < 2; oo++)
#pragma unroll
            for (int d = 0; d < 3; d++)
                g_vout[base + 16 + (part * 2 + oo) * 3 + d] = vv_acc[oo * 3 + d];
    }
}

// ---------------- kernel 3: exp + denom ----------------
__global__ void exp_kernel(const int* __restrict__ eidx) {
    int e = blockIdx.x * 256 + threadIdx.x;
    if (e >= N_EDGES) return;
    int s = eidx[N_EDGES + e];
    float m = dec_f(g_menc[s]);
    float ex = expf(g_attn[e] - m);
    g_ex[e] = ex;
    atomicAdd(&g_denom[s], ex);
}

// ---------------- kernel 4: scatter e*v ----------------
__global__ void scatter_kernel(const int* __restrict__ eidx) {
    int t = blockIdx.x * 256 + threadIdx.x;   // e*40 + j
    if (t >= N_EDGES * 40) return;
    int e = t / 40;
    int j = t - e * 40;
    int s = eidx[N_EDGES + e];
    atomicAdd(&g_upd[(size_t)s * 40 + j], g_ex[e] * g_vout[(size_t)t]);
}

// ---------------- kernel 5: node finalize + bn stats ----------------
__global__ void node_kernel(const float* __restrict__ atom) {
    __shared__ float red[40];
    int t = threadIdx.x;
    if (t < 40) red[t] = 0.f;
    __syncthreads();
    int n = blockIdx.x * 256 + t;
    if (n < N_NODES) {
        float dnm = g_denom[n];
        float inv = dnm > 0.f ? 1.f / dnm : 0.f;
        float y[40];
#pragma unroll
        for (int j = 0; j < 40; j++) {
            y[j] = atom[(size_t)n * 40 + j] + g_upd[(size_t)n * 40 + j] * inv;
            g_upd[(size_t)n * 40 + j] = y[j];
        }
#pragma unroll
        for (int j = 0; j < 16; j++) {
            atomicAdd(&red[j], y[j]);
            atomicAdd(&red[16 + j], y[j] * y[j]);
        }
#pragma unroll
        for (int o = 0; o < 8; o++) {
            float sq = y[16 + o * 3] * y[16 + o * 3]
                     + y[16 + o * 3 + 1] * y[16 + o * 3 + 1]
                     + y[16 + o * 3 + 2] * y[16 + o * 3 + 2];
            atomicAdd(&red[32 + o], sq);
        }
    }
    __syncthreads();
    if (t < 40) atomicAdd(&g_stats[t], red[t]);
}

// ---------------- kernel 6: batchnorm apply ----------------
__global__ void final_kernel(const float* __restrict__ bnws,
                             const float* __restrict__ bnbs,
                             const float* __restrict__ bnwv,
                             float* __restrict__ out, int n_elems) {
    int i = blockIdx.x * 256 + threadIdx.x;
    if (i >= n_elems) return;
    int n = i / 40;
    int j = i - n * 40;
    float y = g_upd[(size_t)i];
    float r;
    if (j < 16) {
        float mu  = g_stats[j] * (1.f / N_NODES);
        float var = g_stats[16 + j] * (1.f / N_NODES) - mu * mu;
        r = (y - mu) * rsqrtf(var + EPSF) * bnws[j] + bnbs[j];
    } else {
        int o = (j - 16) / 3;
        float norm = g_stats[32 + o] * (1.f / (3.f * N_NODES));
        r = y * rsqrtf(norm + EPSF) * bnwv[o];
    }
    out[i] = r;
}

// ---------------- launch ----------------
extern "C" void kernel_launch(void* const* d_in, const int* in_sizes, int n_in,
                              void* d_out, int out_size) {
    const float* atom = (const float*)d_in[0];
    const float* ef   = (const float*)d_in[1];
    const float* sh   = (const float*)d_in[2];
    const float* Wqs  = (const float*)d_in[3];
    const float* Wqv  = (const float*)d_in[4];
    const float* kw1  = (const float*)d_in[5];
    const float* kb1  = (const float*)d_in[6];
    const float* kw2  = (const float*)d_in[7];
    const float* kb2  = (const float*)d_in[8];
    const float* vw1  = (const float*)d_in[9];
    const float* vb1  = (const float*)d_in[10];
    const float* vw2  = (const float*)d_in[11];
    const float* vb2  = (const float*)d_in[12];
    const float* bnws = (const float*)d_in[13];
    const float* bnbs = (const float*)d_in[14];
    const float* bnwv = (const float*)d_in[15];
    const int*   eidx = (const int*)d_in[16];
    float* out = (float*)d_out;

    cudaFuncSetAttribute(edge_kernel, cudaFuncAttributeMaxDynamicSharedMemorySize,
                         (int)sizeof(EK_Smem));

    init_kernel<<<1563, 256>>>();                              // launch 1
    q_kernel<<<(N_NODES + 255) / 256, 256>>>(atom, Wqs, Wqv);  // launch 2
    probe_kernel<<<1, 32>>>();                                 // launch 3 (ncu alignment)
    edge_kernel<<<N_EDGES / 64, 256, sizeof(EK_Smem)>>>(       // launch 4 <- profiled
        atom, ef, sh, kw1, kb1, kw2, kb2, vw1, vb1, vw2, vb2, eidx);
    exp_kernel<<<(N_EDGES + 255) / 256, 256>>>(eidx);
    scatter_kernel<<<(N_EDGES * 40 + 255) / 256, 256>>>(eidx);
    node_kernel<<<(N_NODES + 255) / 256, 256>>>(atom);

    long long ef_elems = (long long)N_EDGES * 32;
    int n_node_elems = out_size;
    bool has_ef = (out_size > ef_elems);
    if (has_ef) n_node_elems = (int)(out_size - ef_elems);

    final_kernel<<<(n_node_elems + 255) / 256, 256>>>(bnws, bnbs, bnwv, out, n_node_elems);
    if (has_ef)
        cudaMemcpyAsync(out + n_node_elems, ef, (size_t)ef_elems * sizeof(float),
                        cudaMemcpyDeviceToDevice);
}

// round 14
// speedup vs baseline: 1.2404x; 1.0088x over previous
#include <cuda_runtime.h>
#include <cstdint>
#include <cstddef>

#define N_NODES 10000
#define N_EDGES 160000
#define C110F 0.57735026918962576f
#define C111F 0.70710678118654752f
#define EPSF  1e-5f

// ---------------- device scratch ----------------
__device__ float    g_q[(size_t)N_NODES * 40];
__device__ float    g_attn[N_EDGES];
__device__ float    g_ex[N_EDGES];
__device__ float    g_vout[(size_t)N_EDGES * 40];
__device__ unsigned g_menc[N_NODES];
__device__ float    g_denom[N_NODES];
__device__ float    g_upd[(size_t)N_NODES * 40];
__device__ float    g_stats[40];   // [0:16) sum_s  [16:32) sumsq_s  [32:40) sum |v|^2

__device__ __forceinline__ unsigned enc_f(float f) {
    unsigned u = __float_as_uint(f);
    return (u & 0x80000000u) ? ~u : (u | 0x80000000u);
}
__device__ __forceinline__ float dec_f(unsigned u) {
    return (u & 0x80000000u) ? __uint_as_float(u ^ 0x80000000u)
                             : __uint_as_float(~u);
}

// ---------------- kernel 0: init ----------------
__global__ void init_kernel() {
    int i = blockIdx.x * 256 + threadIdx.x;
    if (i < N_NODES) { g_menc[i] = 0x007FFFFFu; g_denom[i] = 0.f; }
    if (i < 40) g_stats[i] = 0.f;
    if (i < N_NODES * 40) g_upd[i] = 0.f;
}

// ---------------- probe: keeps edge_kernel as the 4th launch (ncu lands there) ----------------
__global__ void probe_kernel() {}

// ---------------- kernel 1: q = irreps_linear ----------------
__global__ void q_kernel(const float* __restrict__ atom,
                         const float* __restrict__ Wqs,
                         const float* __restrict__ Wqv) {
    __shared__ float ws[256];
    __shared__ float wv[64];
    int t = threadIdx.x;
    ws[t] = Wqs[t];
    if (t < 64) wv[t] = Wqv[t];
    __syncthreads();
    int n = blockIdx.x * 256 + t;
    if (n >= N_NODES) return;
    float x[40];
#pragma unroll
    for (int j = 0; j < 40; j++) x[j] = atom[(size_t)n * 40 + j];
    float q[40];
#pragma unroll
    for (int o = 0; o < 16; o++) {
        float a = 0.f;
#pragma unroll
        for (int i = 0; i < 16; i++) a += x[i] * ws[i * 16 + o];
        q[o] = a;
    }
#pragma unroll
    for (int o = 0; o < 8; o++) {
#pragma unroll
        for (int d = 0; d < 3; d++) {
            float a = 0.f;
#pragma unroll
            for (int i = 0; i < 8; i++) a += x[16 + i * 3 + d] * wv[i * 8 + o];
            q[16 + o * 3 + d] = a;
        }
    }
#pragma unroll
    for (int j = 0; j < 40; j++) g_q[(size_t)n * 40 + j] = q[j];
}

// ---------------- kernel 2: fused edge kernel (occupancy-3 diet) ----------------
struct EK_Smem {
    float Hk[32][68];    // relu(ef@kw1+kb1) transposed [c][e]
    float Hv[32][68];
    float wp[32][68];    // shared W2 panel stage; also efT before layer 1
    float pb[64][68];    // shared panel GEMM output [e][col]
    float pe[64][85];    // per-edge data (odd stride -> conflict-free rows)
    int   dst[64];
    int   src[64];
};
// pe layout: [0:16) q_s | [16:40) q_v o*3+d | [40:56) x_s | [56:80) x_v | [80:84) sh

__global__ void __launch_bounds__(256, 3)
edge_kernel(const float* __restrict__ atom, const float* __restrict__ ef,
            const float* __restrict__ sh,
            const float* __restrict__ kw1, const float* __restrict__ kb1,
            const float* __restrict__ kw2, const float* __restrict__ kb2,
            const float* __restrict__ vw1, const float* __restrict__ vb1,
            const float* __restrict__ vw2, const float* __restrict__ vb2,
            const int* __restrict__ eidx) {
    extern __shared__ char smraw[];
    EK_Smem& sm = *reinterpret_cast<EK_Smem*>(smraw);
    const int tid = threadIdx.x;
    const int e0  = blockIdx.x * 64;

    if (tid < 64)        sm.dst[tid]      = eidx[e0 + tid];
    else if (tid < 128)  sm.src[tid - 64] = eidx[N_EDGES + e0 + (tid - 64)];
    for (int idx = tid; idx < 64 * 32; idx += 256) {
        int e = idx >> 5, c = idx & 31;
        sm.wp[c][e] = ef[(size_t)(e0 + e) * 32 + c];     // efT staged in wp
    }
    __syncthreads();

    // ---- layer 1: H = relu(ef @ w1 + b1), stored transposed ----
    {
        int mat = tid >> 7;           // 0:k 1:v
        int t   = tid & 127;
        int og  = t & 7;              // 4 output cols
        int egg = t >> 3;             // 4 edges
        const float* w1 = mat ? vw1 : kw1;
        const float* b1 = mat ? vb1 : kb1;
        float acc[4][4];
#pragma unroll
        for (int i = 0; i < 4; i++)
#pragma unroll
            for (int j = 0; j < 4; j++) acc[i][j] = 0.f;
#pragma unroll
        for (int c = 0; c < 32; c++) {
            float4 e4 = *reinterpret_cast<const float4*>(&sm.wp[c][egg * 4]);
            float4 w4 = *reinterpret_cast<const float4*>(&w1[c * 32 + og * 4]);
            float ee[4] = {e4.x, e4.y, e4.z, e4.w};
            float ww[4] = {w4.x, w4.y, w4.z, w4.w};
#pragma unroll
            for (int i = 0; i < 4; i++)
#pragma unroll
                for (int j = 0; j < 4; j++) acc[i][j] += ee[i] * ww[j];
        }
        float (*HT)[68] = mat ? sm.Hv : sm.Hk;
#pragma unroll
        for (int j = 0; j < 4; j++) {
            float b = b1[og * 4 + j];
#pragma unroll
            for (int i = 0; i < 4; i++)
                HT[og * 4 + j][egg * 4 + i] = fmaxf(acc[i][j] + b, 0.f);
        }
    }

    // ---- gather per-edge q / x / sh (no precompute; recomputed in consume) ----
    for (int idx = tid; idx < 64 * 40; idx += 256) {
        int e = idx / 40, j = idx - e * 40;
        sm.pe[e][j]      = g_q[(size_t)sm.src[e] * 40 + j];
        sm.pe[e][40 + j] = atom[(size_t)sm.dst[e] * 40 + j];
    }
    if (tid < 64) {
        float4 s4 = *reinterpret_cast<const float4*>(&sh[(size_t)(e0 + tid) * 4]);
        sm.pe[tid][80] = s4.x; sm.pe[tid][81] = s4.y;
        sm.pe[tid][82] = s4.z; sm.pe[tid][83] = s4.w;
    }
    __syncthreads();   // layer1 done reading wp; pe ready

    // GEMM lane mapping (round-11, wavefront-optimal 4x4):
    const int wrp = tid >> 5, lan = tid & 31;
    const int colg = ((wrp & 3) << 2) | (lan & 3);
    const int eg   = ((wrp >> 2) << 3) | (lan >> 2);
    const int e_c = tid >> 2, part = tid & 3;   // consume coords

    float attn_part = 0.f;
    float vs_acc[4] = {0.f, 0.f, 0.f, 0.f};
    float vv_acc[6] = {0.f, 0.f, 0.f, 0.f, 0.f, 0.f};

    // stage k panel 0
    {
#pragma unroll
        for (int k = 0; k < 2; k++) {
            int idx = tid + k * 256;
            int c = idx >> 4, col = (idx & 15) * 4;
            *reinterpret_cast<float4*>(&sm.wp[c][col]) =
                *reinterpret_cast<const float4*>(&kw2[c * 640 + 0 * 64 + col]);
        }
    }
    __syncthreads();

    for (int p = 0; p < 10; p++) {
        // ---- k GEMM: pb = Hk @ wp + kb2 ----
        {
            float acc[4][4];
#pragma unroll
            for (int i = 0; i < 4; i++)
#pragma unroll
                for (int j = 0; j < 4; j++) acc[i][j] = 0.f;
#pragma unroll
            for (int c = 0; c < 32; c++) {
                float4 h4 = *reinterpret_cast<const float4*>(&sm.Hk[c][eg * 4]);
                float4 w4 = *reinterpret_cast<const float4*>(&sm.wp[c][colg * 4]);
                float hh[4] = {h4.x, h4.y, h4.z, h4.w};
                float ww[4] = {w4.x, w4.y, w4.z, w4.w};
#pragma unroll
                for (int i = 0; i < 4; i++)
#pragma unroll
                    for (int j = 0; j < 4; j++) acc[i][j] += hh[i] * ww[j];
            }
            float4 b4 = *reinterpret_cast<const float4*>(&kb2[p * 64 + colg * 4]);
#pragma unroll
            for (int i = 0; i < 4; i++)
                *reinterpret_cast<float4*>(&sm.pb[eg * 4 + i][colg * 4]) =
                    make_float4(acc[i][0] + b4.x, acc[i][1] + b4.y,
                                acc[i][2] + b4.z, acc[i][3] + b4.w);
        }
        __syncthreads();

        // ---- consume k (attn) + stage v panel ----
        {
            float* pe = sm.pe[e_c];
            float* pb = sm.pb[e_c];
            float shs = pe[80], sv0 = pe[81], sv1 = pe[82], sv2 = pe[83];
            if (p < 6) {
                float q0 = pe[part * 4 + 0], q1 = pe[part * 4 + 1];
                float q2 = pe[part * 4 + 2], q3 = pe[part * 4 + 3];
#pragma unroll
                for (int ii = 0; ii < 4; ii++) {
                    float fac;
                    if (p < 4) fac = pe[40 + p * 4 + ii] * shs;
                    else {
                        int i = (p - 4) * 4 + ii;
                        fac = C110F * (pe[56 + i * 3] * sv0 + pe[56 + i * 3 + 1] * sv1
                                       + pe[56 + i * 3 + 2] * sv2);
                    }
                    float4 w4 = *reinterpret_cast<const float4*>(&pb[ii * 16 + part * 4]);
                    attn_part += fac * (w4.x * q0 + w4.y * q1 + w4.z * q2 + w4.w * q3);
                }
            } else {
                int oA = part * 2, oB = oA + 1;
                float qA0 = pe[16 + oA * 3], qA1 = pe[16 + oA * 3 + 1], qA2 = pe[16 + oA * 3 + 2];
                float qB0 = pe[16 + oB * 3], qB1 = pe[16 + oB * 3 + 1], qB2 = pe[16 + oB * 3 + 2];
                float qsA = qA0 * sv0 + qA1 * sv1 + qA2 * sv2;
                float qsB = qB0 * sv0 + qB1 * sv1 + qB2 * sv2;
#pragma unroll
                for (int ii = 0; ii < 8; ii++) {
                    float2 w2 = *reinterpret_cast<const float2*>(&pb[ii * 8 + oA]);
                    float wa = w2.x, wb = w2.y;
                    if (p < 8) {
                        float xs = pe[40 + (p - 6) * 8 + ii];
                        attn_part += xs * (wa * qsA + wb * qsB);
                    } else {
                        float a0 = pe[56 + ii * 3], a1 = pe[56 + ii * 3 + 1], a2 = pe[56 + ii * 3 + 2];
                        float v0, v1, v2, ca, cb;
                        if (p == 8) { v0 = a0; v1 = a1; v2 = a2; ca = wa * shs; cb = wb * shs; }
                        else {
                            v0 = a1 * sv2 - a2 * sv1;
                            v1 = a2 * sv0 - a0 * sv2;
                            v2 = a0 * sv1 - a1 * sv0;
                            ca = wa * C111F; cb = wb * C111F;
                        }
                        attn_part += ca * (v0 * qA0 + v1 * qA1 + v2 * qA2)
                                   + cb * (v0 * qB0 + v1 * qB1 + v2 * qB2);
                    }
                }
            }
        }
        {
#pragma unroll
            for (int k = 0; k < 2; k++) {
                int idx = tid + k * 256;
                int c = idx >> 4, col = (idx & 15) * 4;
                *reinterpret_cast<float4*>(&sm.wp[c][col]) =
                    *reinterpret_cast<const float4*>(&vw2[c * 640 + p * 64 + col]);
            }
        }
        __syncthreads();

        // ---- v GEMM: pb = Hv @ wp + vb2 ----
        {
            float acc[4][4];
#pragma unroll
            for (int i = 0; i < 4; i++)
#pragma unroll
                for (int j = 0; j < 4; j++) acc[i][j] = 0.f;
#pragma unroll
            for (int c = 0; c < 32; c++) {
                float4 h4 = *reinterpret_cast<const float4*>(&sm.Hv[c][eg * 4]);
                float4 w4 = *reinterpret_cast<const float4*>(&sm.wp[c][colg * 4]);
                float hh[4] = {h4.x, h4.y, h4.z, h4.w};
                float ww[4] = {w4.x, w4.y, w4.z, w4.w};
#pragma unroll
                for (int i = 0; i < 4; i++)
#pragma unroll
                    for (int j = 0; j < 4; j++) acc[i][j] += hh[i] * ww[j];
            }
            float4 b4 = *reinterpret_cast<const float4*>(&vb2[p * 64 + colg * 4]);
#pragma unroll
            for (int i = 0; i < 4; i++)
                *reinterpret_cast<float4*>(&sm.pb[eg * 4 + i][colg * 4]) =
                    make_float4(acc[i][0] + b4.x, acc[i][1] + b4.y,
                                acc[i][2] + b4.z, acc[i][3] + b4.w);
        }
        __syncthreads();

        // ---- consume v (vs/vv) + stage next k panel ----
        {
            float* pe = sm.pe[e_c];
            float* pb = sm.pb[e_c];
            float shs = pe[80], sv0 = pe[81], sv1 = pe[82], sv2 = pe[83];
            if (p < 6) {
#pragma unroll
                for (int ii = 0; ii < 4; ii++) {
                    float fac;
                    if (p < 4) fac = pe[40 + p * 4 + ii] * shs;
                    else {
                        int i = (p - 4) * 4 + ii;
                        fac = C110F * (pe[56 + i * 3] * sv0 + pe[56 + i * 3 + 1] * sv1
                                       + pe[56 + i * 3 + 2] * sv2);
                    }
                    float4 w4 = *reinterpret_cast<const float4*>(&pb[ii * 16 + part * 4]);
                    vs_acc[0] += w4.x * fac; vs_acc[1] += w4.y * fac;
                    vs_acc[2] += w4.z * fac; vs_acc[3] += w4.w * fac;
                }
            } else {
                int oA = part * 2;
#pragma unroll
                for (int ii = 0; ii < 8; ii++) {
                    float2 w2 = *reinterpret_cast<const float2*>(&pb[ii * 8 + oA]);
                    float wa = w2.x, wb = w2.y;
                    if (p < 8) {
                        float xs = pe[40 + (p - 6) * 8 + ii];
                        float ta = wa * xs, tb = wb * xs;
                        vv_acc[0] += ta * sv0; vv_acc[1] += ta * sv1; vv_acc[2] += ta * sv2;
                        vv_acc[3] += tb * sv0; vv_acc[4] += tb * sv1; vv_acc[5] += tb * sv2;
                    } else {
                        float a0 = pe[56 + ii * 3], a1 = pe[56 + ii * 3 + 1], a2 = pe[56 + ii * 3 + 2];
                        float v0, v1, v2, ca, cb;
                        if (p == 8) { v0 = a0; v1 = a1; v2 = a2; ca = wa * shs; cb = wb * shs; }
                        else {
                            v0 = a1 * sv2 - a2 * sv1;
                            v1 = a2 * sv0 - a0 * sv2;
                            v2 = a0 * sv1 - a1 * sv0;
                            ca = wa * C111F; cb = wb * C111F;
                        }
                        vv_acc[0] += ca * v0; vv_acc[1] += ca * v1; vv_acc[2] += ca * v2;
                        vv_acc[3] += cb * v0; vv_acc[4] += cb * v1; vv_acc[5] += cb * v2;
                    }
                }
            }
        }
        if (p < 9) {
#pragma unroll
            for (int k = 0; k < 2; k++) {
                int idx = tid + k * 256;
                int c = idx >> 4, col = (idx & 15) * 4;
                *reinterpret_cast<float4*>(&sm.wp[c][col]) =
                    *reinterpret_cast<const float4*>(&kw2[c * 640 + (p + 1) * 64 + col]);
            }
        }
        __syncthreads();
    } // panels

    // finalize attn
    {
        float a = attn_part;
        a += __shfl_down_sync(0xffffffffu, a, 2, 4);
        a += __shfl_down_sync(0xffffffffu, a, 1, 4);
        if (part == 0) {
            g_attn[e0 + e_c] = a;
            atomicMax(&g_menc[sm.src[e_c]], enc_f(a));
        }
    }
    // finalize v
    {
        size_t base = (size_t)(e0 + e_c) * 40;
#pragma unroll
        for (int j = 0; j < 4; j++) g_vout[base + part * 4 + j] = vs_acc[j];
#pragma unroll
        for (int oo = 0; oo < 2; oo++)
#pragma unroll
            for (int d = 0; d < 3; d++)
                g_vout[base + 16 + (part * 2 + oo) * 3 + d] = vv_acc[oo * 3 + d];
    }
}

// ---------------- kernel 3: exp + denom ----------------
__global__ void exp_kernel(const int* __restrict__ eidx) {
    int e = blockIdx.x * 256 + threadIdx.x;
    if (e >= N_EDGES) return;
    int s = eidx[N_EDGES + e];
    float m = dec_f(g_menc[s]);
    float ex = expf(g_attn[e] - m);
    g_ex[e] = ex;
    atomicAdd(&g_denom[s], ex);
}

// ---------------- kernel 4: scatter e*v ----------------
__global__ void scatter_kernel(const int* __restrict__ eidx) {
    int t = blockIdx.x * 256 + threadIdx.x;   // e*40 + j
    if (t >= N_EDGES * 40) return;
    int e = t / 40;
    int j = t - e * 40;
    int s = eidx[N_EDGES + e];
    atomicAdd(&g_upd[(size_t)s * 40 + j], g_ex[e] * g_vout[(size_t)t]);
}

// ---------------- kernel 5: node finalize + bn stats ----------------
__global__ void node_kernel(const float* __restrict__ atom) {
    __shared__ float red[40];
    int t = threadIdx.x;
    if (t < 40) red[t] = 0.f;
    __syncthreads();
    int n = blockIdx.x * 256 + t;
    if (n < N_NODES) {
        float dnm = g_denom[n];
        float inv = dnm > 0.f ? 1.f / dnm : 0.f;
        float y[40];
#pragma unroll
        for (int j = 0; j < 40; j++) {
            y[j] = atom[(size_t)n * 40 + j] + g_upd[(size_t)n * 40 + j] * inv;
            g_upd[(size_t)n * 40 + j] = y[j];
        }
#pragma unroll
        for (int j = 0; j < 16; j++) {
            atomicAdd(&red[j], y[j]);
            atomicAdd(&red[16 + j], y[j] * y[j]);
        }
#pragma unroll
        for (int o = 0; o < 8; o++) {
            float sq = y[16 + o * 3] * y[16 + o * 3]
                     + y[16 + o * 3 + 1] * y[16 + o * 3 + 1]
                     + y[16 + o * 3 + 2] * y[16 + o * 3 + 2];
            atomicAdd(&red[32 + o], sq);
        }
    }
    __syncthreads();
    if (t < 40) atomicAdd(&g_stats[t], red[t]);
}

// ---------------- kernel 6: batchnorm apply ----------------
__global__ void final_kernel(const float* __restrict__ bnws,
                             const float* __restrict__ bnbs,
                             const float* __restrict__ bnwv,
                             float* __restrict__ out, int n_elems) {
    int i = blockIdx.x * 256 + threadIdx.x;
    if (i >= n_elems) return;
    int n = i / 40;
    int j = i - n * 40;
    float y = g_upd[(size_t)i];
    float r;
    if (j < 16) {
        float mu  = g_stats[j] * (1.f / N_NODES);
        float var = g_stats[16 + j] * (1.f / N_NODES) - mu * mu;
        r = (y - mu) * rsqrtf(var + EPSF) * bnws[j] + bnbs[j];
    } else {
        int o = (j - 16) / 3;
        float norm = g_stats[32 + o] * (1.f / (3.f * N_NODES));
        r = y * rsqrtf(norm + EPSF) * bnwv[o];
    }
    out[i] = r;
}

// ---------------- launch ----------------
extern "C" void kernel_launch(void* const* d_in, const int* in_sizes, int n_in,
                              void* d_out, int out_size) {
    const float* atom = (const float*)d_in[0];
    const float* ef   = (const float*)d_in[1];
    const float* sh   = (const float*)d_in[2];
    const float* Wqs  = (const float*)d_in[3];
    const float* Wqv  = (const float*)d_in[4];
    const float* kw1  = (const float*)d_in[5];
    const float* kb1  = (const float*)d_in[6];
    const float* kw2  = (const float*)d_in[7];
    const float* kb2  = (const float*)d_in[8];
    const float* vw1  = (const float*)d_in[9];
    const float* vb1  = (const float*)d_in[10];
    const float* vw2  = (const float*)d_in[11];
    const float* vb2  = (const float*)d_in[12];
    const float* bnws = (const float*)d_in[13];
    const float* bnbs = (const float*)d_in[14];
    const float* bnwv = (const float*)d_in[15];
    const int*   eidx = (const int*)d_in[16];
    float* out = (float*)d_out;

    cudaFuncSetAttribute(edge_kernel, cudaFuncAttributeMaxDynamicSharedMemorySize,
                         (int)sizeof(EK_Smem));

    init_kernel<<<1563, 256>>>();                              // launch 1
    q_kernel<<<(N_NODES + 255) / 256, 256>>>(atom, Wqs, Wqv);  // launch 2
    probe_kernel<<<1, 32>>>();                                 // launch 3 (ncu alignment)
    edge_kernel<<<N_EDGES / 64, 256, sizeof(EK_Smem)>>>(       // launch 4 <- profiled
        atom, ef, sh, kw1, kb1, kw2, kb2, vw1, vb1, vw2, vb2, eidx);
    exp_kernel<<<(N_EDGES + 255) / 256, 256>>>(eidx);
    scatter_kernel<<<(N_EDGES * 40 + 255) / 256, 256>>>(eidx);
    node_kernel<<<(N_NODES + 255) / 256, 256>>>(atom);

    long long ef_elems = (long long)N_EDGES * 32;
    int n_node_elems = out_size;
    bool has_ef = (out_size > ef_elems);
    if (has_ef) n_node_elems = (int)(out_size - ef_elems);

    final_kernel<<<(n_node_elems + 255) / 256, 256>>>(bnws, bnbs, bnwv, out, n_node_elems);
    if (has_ef)
        cudaMemcpyAsync(out + n_node_elems, ef, (size_t)ef_elems * sizeof(float),
                        cudaMemcpyDeviceToDevice);
}